// round 15
// baseline (speedup 1.0000x reference)
#include <cuda_runtime.h>
#include <math.h>

#define BS 16
#define QN 900
#define NC 92
#define TN 256
#define NQT (BS*QN)        // 14400
#define NT  (BS*TN)        // 4096
#define C_ELEMS (NQT*NT)   // 58,982,400

#define FP_SCALE_F 1099511627776.0f   // 2^40
#define I64_INF  (1LL<<62)
#define DINF_D   (1LL<<52)
#define KEY_MAX  0x7FFFFFFFFFFFFFFFLL
#define KEY_BIAS (1LL<<45)
#define NDIAG    912                  // 57 diag tiles * 16 batches
#define NGROUP   3600                 // 900 itiles * 4 jtile-groups

// ---------------- scratch ----------------------------------------------------
__device__ float      g_prob[NQT*NC];
__device__ float      g_predf[NQT*12];
__device__ float      g_tgtf[NT*12];
__device__ int        g_tlab[NT];
__device__ long long  g_Ci[BS*TN*QN];     // [b][t][q] int64 fixed-point
__device__ long long  g_rowkey[BS*TN];
__device__ int        g_diag_cnt[BS];

__device__ __forceinline__ int tmin_of(int b) { return (900 * b) >> 4; }
__device__ __forceinline__ int tmax_of(int b) { return (900 * b + 899) >> 4; }

#define SMEM_BYTES 24192   // max(LSA ~20.8KB, diag-cost 24064)

// ---------------- prep + softmax (fused launch) -------------------------------
__global__ void prep_softmax_k(const float* __restrict__ logits,
                               const float* __restrict__ pb,
                               const float* __restrict__ tb,
                               const int*   __restrict__ tl) {
    int bid = blockIdx.x;
    if (bid < 57) {                      // prep part
        int i = bid * 256 + threadIdx.x;
        if (i < BS) g_diag_cnt[i] = 0;
        if (i < NQT) {
            float cx = pb[i*4+0], cy = pb[i*4+1], w = pb[i*4+2], h = pb[i*4+3];
            float x0 = cx - 0.5f*w, y0 = cy - 0.5f*h, x1 = cx + 0.5f*w, y1 = cy + 0.5f*h;
            float* o = &g_predf[i*12];
            o[0]=cx; o[1]=cy; o[2]=w; o[3]=h;
            o[4]=x0; o[5]=y0; o[6]=x1; o[7]=y1;
            o[8]=(x1-x0)*(y1-y0);
        }
        if (i < NT) {
            float cx = tb[i*4+0], cy = tb[i*4+1], w = tb[i*4+2], h = tb[i*4+3];
            float x0 = cx - 0.5f*w, y0 = cy - 0.5f*h, x1 = cx + 0.5f*w, y1 = cy + 0.5f*h;
            float* o = &g_tgtf[i*12];
            o[0]=cx; o[1]=cy; o[2]=w; o[3]=h;
            o[4]=x0; o[5]=y0; o[6]=x1; o[7]=y1;
            o[8]=(x1-x0)*(y1-y0);
            g_tlab[i] = tl[i];
            g_rowkey[i] = I64_INF;
        }
        return;
    }
    // softmax: one warp per row of 92 logits
    int warp = (bid - 57) * 8 + (threadIdx.x >> 5);
    int lane = threadIdx.x & 31;
    if (warp >= NQT) return;
    const float* row = logits + warp * NC;
    float v0 = row[lane];
    float v1 = row[lane + 32];
    float v2 = (lane + 64 < NC) ? row[lane + 64] : -INFINITY;
    float m = fmaxf(v0, fmaxf(v1, v2));
    #pragma unroll
    for (int o = 16; o; o >>= 1) m = fmaxf(m, __shfl_xor_sync(0xffffffffu, m, o));
    float e0 = expf(v0 - m), e1 = expf(v1 - m), e2 = expf(v2 - m);
    float s = e0 + e1 + e2;
    #pragma unroll
    for (int o = 16; o; o >>= 1) s += __shfl_xor_sync(0xffffffffu, s, o);
    float* op = g_prob + warp * NC;
    op[lane]      = e0 / s;
    op[lane + 32] = e1 / s;
    if (lane + 64 < NC) op[lane + 64] = e2 / s;
}

// ---------------- cost-pair math (single-div GIoU, FADD.SAT clamps) ----------
__device__ __forceinline__ float cost_pair(const float* __restrict__ spred, int ii,
                                           float prob, float4 tc, float4 txy, float tarea) {
    float4 pc  = *(const float4*)&spred[ii * 12];
    float4 pxy = *(const float4*)&spred[ii * 12 + 4];
    float  parea = spred[ii * 12 + 8];

    float l1 = fabsf(pc.x - tc.x) + fabsf(pc.y - tc.y)
             + fabsf(pc.z - tc.z) + fabsf(pc.w - tc.w);

    float ltx = fmaxf(pxy.x, txy.x), lty = fmaxf(pxy.y, txy.y);
    float rbx = fminf(pxy.z, txy.z), rby = fminf(pxy.w, txy.w);
    float iw = __saturatef(rbx - ltx), ih = __saturatef(rby - lty);
    float inter = iw * ih;
    float uni = parea + tarea - inter;

    float ex0 = fminf(pxy.x, txy.x), ey0 = fminf(pxy.y, txy.y);
    float ex1 = fmaxf(pxy.z, txy.z), ey1 = fmaxf(pxy.w, txy.w);
    float earea = (ex1 - ex0) * (ey1 - ey0);

    float s = __fdividef(fmaf(uni, uni, inter * earea), uni * earea);
    return fmaf(-2.0f, s, fmaf(5.0f, l1, 2.0f - prob));
}

// ---------------- shared preload (sprob + spred for one itile) ---------------
__device__ __forceinline__ void preload_tile(int i0, float* sprob, float* spred) {
    int tid = threadIdx.x;
    for (int k = tid; k < 16 * NC; k += 256) sprob[k] = g_prob[i0 * NC + k];
    for (int k = tid; k < 16 * 12; k += 256) spred[k] = g_predf[i0 * 12 + k];
    __syncthreads();
}

// ---------------- off-diag inner (one jtile, data preloaded) -----------------
__device__ __forceinline__ void offdiag_inner(int i0, int jtile,
                                              const float* sprob, const float* spred,
                                              float* __restrict__ outC) {
    int tid = threadIdx.x;
    int jg  = (jtile << 8) + tid;

    const float4* tf = (const float4*)&g_tgtf[jg * 12];
    float4 tc = tf[0];
    float4 txy = tf[1];
    float  tarea = g_tgtf[jg * 12 + 8];
    int    lab   = g_tlab[jg];
    const float* prp = sprob + lab;

    float* op = outC + (size_t)i0 * NT + jg;
    #pragma unroll 4
    for (int ii = 0; ii < 16; ii++) {
        float c = cost_pair(spred, ii, prp[ii * NC], tc, txy, tarea);
        __stcs(&op[(size_t)ii * NT], c);     // streaming store
    }
}

// ---------------- diag tile (own blocks; early LSA handoff) ------------------
__device__ __forceinline__ void diag_tile(int itile, int b,
                                          float* __restrict__ outC,
                                          unsigned char* sm) {
    float* sprob = (float*)sm;                  // 5888 B
    float* spred = (float*)(sm + 5888);         // 768 B
    float* stile = (float*)(sm + 6656);         // 256*17*4

    int tid = threadIdx.x;
    int jg  = (b << 8) + tid;
    int i0  = itile * 16;

    preload_tile(i0, sprob, spred);

    const float4* tf = (const float4*)&g_tgtf[jg * 12];
    float4 tc = tf[0];
    float4 txy = tf[1];
    float  tarea = g_tgtf[jg * 12 + 8];
    int    lab   = g_tlab[jg];
    const float* prp = sprob + lab;

    int iiA = b * QN - i0;           if (iiA < 0)  iiA = 0;
    int iiB = b * QN + QN - 1 - i0;  if (iiB > 15) iiB = 15;

    float* op = outC + (size_t)i0 * NT + jg;
    long long bestkey = I64_INF;
    #pragma unroll 4
    for (int ii = 0; ii < 16; ii++) {
        float c = cost_pair(spred, ii, prp[ii * NC], tc, txy, tarea);
        op[(size_t)ii * NT] = c;
        stile[tid * 17 + ii] = c;
        if (ii >= iiA && ii <= iiB) {
            long long ci = llrintf(c * FP_SCALE_F);
            int q = i0 + ii - b * QN;
            long long key = ((ci + KEY_BIAS) << 10) | (long long)q;
            if (key < bestkey) bestkey = key;
        }
    }
    if (bestkey != I64_INF) atomicMin(&g_rowkey[jg], bestkey);
    __syncthreads();

    for (int e = tid; e < 256 * 16; e += 256) {
        int t = e >> 4, ii = e & 15;
        if (ii >= iiA && ii <= iiB) {
            int q = i0 + ii - b * QN;
            g_Ci[(size_t)((b << 8) + t) * QN + q] = llrintf(stile[t * 17 + ii] * FP_SCALE_F);
        }
    }

    __threadfence();
    __syncthreads();
    if (tid == 0) atomicAdd(&g_diag_cnt[b], 1);
}

// ---------------- LSA: seed -> augmenting row reduction -> Dijkstra ---------
__device__ void lsa_block(int b, float* __restrict__ out, unsigned char* sm) {
    const int tid  = threadIdx.x;
    const int lane = tid & 31;
    const int wrp  = tid >> 5;
    const long long* Cb = g_Ci + (size_t)b * TN * QN;
    const bool has3 = (tid + 768) < QN;
    const int j3 = tid + 768;

    long long* sv    = (long long*)sm;            // 7200
    long long* su    = (long long*)(sm + 7200);   // 2048
    long long* w1    = (long long*)(sm + 9248);   // 64
    long long* w2    = (long long*)(sm + 9312);   // 64
    long long* wkey  = (long long*)(sm + 9376);   // 128
    int*       sp    = (int*)(sm + 9504);         // 3600
    int*       sway  = (int*)(sm + 13104);        // 3600
    int*       spend = (int*)(sm + 16704);        // 4096
    int*       sq    = (int*)(sm + 20800);        // 8

    // wait for this batch's diagonal tiles
    if (tid == 0) {
        while (*(volatile int*)&g_diag_cnt[b] < 57) __nanosleep(100);
    }
    __syncthreads();
    __threadfence();

    for (int j = tid; j < QN; j += 256) { sp[j] = 0; sv[j] = 0; }
    for (int i = tid; i < TN; i += 256)
        su[i] = (g_rowkey[b * TN + i] >> 10) - KEY_BIAS;
    __syncthreads();

    // greedy seeding
    if (tid == 0) {
        int np = 0;
        for (int i = 0; i < TN; i++) {
            int j = (int)(g_rowkey[b * TN + i] & 1023LL);
            if (sp[j] == 0) sp[j] = i + 1;
            else spend[np++] = i;
        }
        sq[0] = 0; sq[1] = np;
    }

    // augmenting row reduction (LAPJV-style, capped)
    int iter = 0;
    while (true) {
        __syncthreads();
        int qh = sq[0], qt = sq[1];
        if (qh >= qt || iter >= 740) break;
        iter++;
        int i = spend[qh];
        const long long* row = Cb + (size_t)i * QN;

        long long k1, k2;
        {
            long long c0 = ((row[tid]       - sv[tid])       << 10) | (long long)tid;
            long long c1 = ((row[tid + 256] - sv[tid + 256]) << 10) | (long long)(tid + 256);
            long long c2 = ((row[tid + 512] - sv[tid + 512]) << 10) | (long long)(tid + 512);
            k1 = c0 < c1 ? c0 : c1;  k2 = c0 < c1 ? c1 : c0;
            if (c2 < k1) { k2 = k1; k1 = c2; } else if (c2 < k2) k2 = c2;
            if (has3) {
                long long c3 = ((row[j3] - sv[j3]) << 10) | (long long)j3;
                if (c3 < k1) { k2 = k1; k1 = c3; } else if (c3 < k2) k2 = c3;
            }
        }
        #pragma unroll
        for (int o = 16; o; o >>= 1) {
            long long o1 = __shfl_down_sync(0xffffffffu, k1, o);
            long long o2 = __shfl_down_sync(0xffffffffu, k2, o);
            long long n1 = k1 < o1 ? k1 : o1;
            long long hi = k1 < o1 ? o1 : k1;
            long long lo2 = k2 < o2 ? k2 : o2;
            k1 = n1; k2 = hi < lo2 ? hi : lo2;
        }
        if (lane == 0) { w1[wrp] = k1; w2[wrp] = k2; }
        __syncthreads();
        if (tid == 0) {
            long long m1 = w1[0], m2 = w2[0];
            #pragma unroll
            for (int w = 1; w < 8; w++) {
                long long a1 = w1[w], a2 = w2[w];
                long long n1 = m1 < a1 ? m1 : a1;
                long long hi = m1 < a1 ? a1 : m1;
                long long lo2 = m2 < a2 ? m2 : a2;
                m1 = n1; m2 = hi < lo2 ? hi : lo2;
            }
            int j1 = (int)(m1 & 1023LL);
            long long u1 = m1 >> 10, u2 = m2 >> 10;
            int i0 = sp[j1];
            if (u1 < u2) sv[j1] -= (u2 - u1);
            else if (i0 > 0) { j1 = (int)(m2 & 1023LL); i0 = sp[j1]; }
            sp[j1] = i + 1;
            su[i] = u2;
            sq[0] = qh + 1;
            if (i0 > 0) { spend[qt] = i0 - 1; sq[1] = qt + 1; }
        }
    }
    __syncthreads();

    // Dijkstra shortest augmenting paths for leftovers
    long long v[4];
    v[0] = sv[tid]; v[1] = sv[tid + 256]; v[2] = sv[tid + 512];
    v[3] = has3 ? sv[j3] : 0;

    int qh = sq[0], qt = sq[1];
    for (int pi = qh; pi < qt; pi++) {
        int istart = spend[pi];
        long long dist[4];
        dist[0] = dist[1] = dist[2] = dist[3] = DINF_D;
        unsigned usedm = 0;
        int buf = 0;

        long long bv = 0;
        int i0r = istart, j0 = -1;
        int sink; long long minVal;

        while (true) {
            long long base = bv - su[i0r];
            const long long* row = Cb + (size_t)i0r * QN;

            long long c0 = base + row[tid] - v[0];
            if (c0 < dist[0]) { dist[0] = c0; sway[tid] = j0; }
            long long c1 = base + row[tid + 256] - v[1];
            if (c1 < dist[1]) { dist[1] = c1; sway[tid + 256] = j0; }
            long long c2 = base + row[tid + 512] - v[2];
            if (c2 < dist[2]) { dist[2] = c2; sway[tid + 512] = j0; }
            if (has3) {
                long long c3 = base + row[j3] - v[3];
                if (c3 < dist[3]) { dist[3] = c3; sway[j3] = j0; }
            }
            long long k0 = (usedm & 1u) ? KEY_MAX : ((dist[0] << 10) | (long long)tid);
            long long k1 = (usedm & 2u) ? KEY_MAX : ((dist[1] << 10) | (long long)(tid + 256));
            long long k2 = (usedm & 4u) ? KEY_MAX : ((dist[2] << 10) | (long long)(tid + 512));
            long long k3 = (!has3 || (usedm & 8u)) ? KEY_MAX : ((dist[3] << 10) | (long long)j3);
            long long lb = k0 < k1 ? k0 : k1;
            long long lc = k2 < k3 ? k2 : k3;
            lb = lb < lc ? lb : lc;
            #pragma unroll
            for (int o = 16; o; o >>= 1) {
                long long ov = __shfl_down_sync(0xffffffffu, lb, o);
                lb = ov < lb ? ov : lb;
            }
            if (lane == 0) wkey[buf * 8 + wrp] = lb;
            __syncthreads();
            long long mk = wkey[buf * 8];
            #pragma unroll
            for (int w = 1; w < 8; w++) { long long a = wkey[buf * 8 + w]; mk = a < mk ? a : mk; }
            buf ^= 1;

            int jj = (int)(mk & 1023LL);
            bv = mk >> 10;
            if ((jj & 255) == tid) usedm |= 1u << (jj >> 8);
            int r = sp[jj];
            if (r == 0) { sink = jj; minVal = bv; break; }
            j0 = jj; i0r = r - 1;
        }

        #pragma unroll
        for (int k = 0; k < 4; k++) {
            if (usedm & (1u << k)) {
                int j = tid + (k << 8);
                long long d = dist[k];
                v[k] += d - minVal;
                su[sp[j] - 1] += minVal - d;
            }
        }
        __syncthreads();
        if (tid == 0) {
            su[istart] += minVal;
            int j = sink;
            while (true) {
                int jp = sway[j];
                if (jp < 0) { sp[j] = istart + 1; break; }
                sp[j] = sp[jp];
                j = jp;
            }
        }
        __syncthreads();
    }

    if (tid == 0) {
        float* rows = out + (size_t)C_ELEMS + b * TN;
        float* cols = out + (size_t)C_ELEMS + NT + b * TN;
        int k = 0;
        for (int j = 0; j < QN; j++) {
            if (sp[j]) { rows[k] = (float)j; cols[k] = (float)(sp[j] - 1); k++; }
        }
    }
}

// ---------------- fully fused kernel ------------------------------------------
__global__ void __launch_bounds__(256, 6) fused_k(float* __restrict__ outC) {
    __shared__ __align__(16) unsigned char smraw[SMEM_BYTES];
    int bid = blockIdx.x;

    if (bid < 16) { lsa_block(bid, outC, smraw); return; }

    if (bid < 16 + NDIAG) {                  // diagonal tiles (own blocks)
        int idx = bid - 16;
        int b = idx / 57;
        int itile = tmin_of(b) + idx % 57;
        diag_tile(itile, b, outC, smraw);
        return;
    }

    // off-diagonal groups: 4 jtiles per block, one preload
    int g = bid - (16 + NDIAG);
    int itile = g >> 2;
    int jbase = (g & 3) << 2;
    int i0 = itile * 16;

    float* sprob = (float*)smraw;
    float* spred = (float*)(smraw + 5888);
    preload_tile(i0, sprob, spred);

    #pragma unroll
    for (int jt = jbase; jt < jbase + 4; jt++) {
        if (itile >= tmin_of(jt) && itile <= tmax_of(jt)) continue;  // diag done elsewhere
        offdiag_inner(i0, jt, sprob, spred, outC);
    }
}

// ---------------- launch -----------------------------------------------------
extern "C" void kernel_launch(void* const* d_in, const int* in_sizes, int n_in,
                              void* d_out, int out_size) {
    const float* logits = (const float*)d_in[0];
    const float* pboxes = (const float*)d_in[1];
    const int*   tlab   = (const int*)  d_in[2];
    const float* tbox   = (const float*)d_in[3];
    float* out = (float*)d_out;

    prep_softmax_k<<<57 + 1800, 256>>>(logits, pboxes, tbox, tlab);
    fused_k<<<16 + NDIAG + NGROUP, 256>>>(out);
}

// round 17
// speedup vs baseline: 1.0093x; 1.0093x over previous
#include <cuda_runtime.h>
#include <cstdint>
#include <math.h>

#define BS 16
#define QN 900
#define NC 92
#define TN 256
#define NQT (BS*QN)        // 14400
#define NT  (BS*TN)        // 4096
#define C_ELEMS (NQT*NT)   // 58,982,400

#define FP_SCALE_F 1099511627776.0f   // 2^40
#define I64_INF  (1LL<<62)
#define DINF_D   (1LL<<52)
#define KEY_MAX  0x7FFFFFFFFFFFFFFFLL
#define KEY_BIAS (1LL<<45)
#define NDIAG    912                  // 57 diag tiles * 16 batches

// ---------------- scratch ----------------------------------------------------
__device__ float      g_prob[NQT*NC];
__device__ float      g_predf[NQT*12];
__device__ float      g_tgtf[NT*12];
__device__ int        g_tlab[NT];
__device__ __align__(16) long long g_Ci[BS*TN*QN + 256];  // +pad for prefetch overrun
__device__ long long  g_rowkey[BS*TN];
__device__ int        g_diag_cnt[BS];

__device__ __forceinline__ int tmin_of(int b) { return (900 * b) >> 4; }
__device__ __forceinline__ int tmax_of(int b) { return (900 * b + 899) >> 4; }

// LSA: 20832 state + 2*8192 prefetch buffers = 37216; diag-cost needs 24064
#define SMEM_BYTES 37248
#define BUF_OFF    20832

// ---------------- prep + softmax (fused launch) -------------------------------
__global__ void prep_softmax_k(const float* __restrict__ logits,
                               const float* __restrict__ pb,
                               const float* __restrict__ tb,
                               const int*   __restrict__ tl) {
    int bid = blockIdx.x;
    if (bid < 57) {                      // prep part
        int i = bid * 256 + threadIdx.x;
        if (i < BS) g_diag_cnt[i] = 0;
        if (i < NQT) {
            float cx = pb[i*4+0], cy = pb[i*4+1], w = pb[i*4+2], h = pb[i*4+3];
            float x0 = cx - 0.5f*w, y0 = cy - 0.5f*h, x1 = cx + 0.5f*w, y1 = cy + 0.5f*h;
            float* o = &g_predf[i*12];
            o[0]=cx; o[1]=cy; o[2]=w; o[3]=h;
            o[4]=x0; o[5]=y0; o[6]=x1; o[7]=y1;
            o[8]=(x1-x0)*(y1-y0);
        }
        if (i < NT) {
            float cx = tb[i*4+0], cy = tb[i*4+1], w = tb[i*4+2], h = tb[i*4+3];
            float x0 = cx - 0.5f*w, y0 = cy - 0.5f*h, x1 = cx + 0.5f*w, y1 = cy + 0.5f*h;
            float* o = &g_tgtf[i*12];
            o[0]=cx; o[1]=cy; o[2]=w; o[3]=h;
            o[4]=x0; o[5]=y0; o[6]=x1; o[7]=y1;
            o[8]=(x1-x0)*(y1-y0);
            g_tlab[i] = tl[i];
            g_rowkey[i] = I64_INF;
        }
        return;
    }
    // softmax: one warp per row of 92 logits
    int warp = (bid - 57) * 8 + (threadIdx.x >> 5);
    int lane = threadIdx.x & 31;
    if (warp >= NQT) return;
    const float* row = logits + warp * NC;
    float v0 = row[lane];
    float v1 = row[lane + 32];
    float v2 = (lane + 64 < NC) ? row[lane + 64] : -INFINITY;
    float m = fmaxf(v0, fmaxf(v1, v2));
    #pragma unroll
    for (int o = 16; o; o >>= 1) m = fmaxf(m, __shfl_xor_sync(0xffffffffu, m, o));
    float e0 = expf(v0 - m), e1 = expf(v1 - m), e2 = expf(v2 - m);
    float s = e0 + e1 + e2;
    #pragma unroll
    for (int o = 16; o; o >>= 1) s += __shfl_xor_sync(0xffffffffu, s, o);
    float* op = g_prob + warp * NC;
    op[lane]      = e0 / s;
    op[lane + 32] = e1 / s;
    if (lane + 64 < NC) op[lane + 64] = e2 / s;
}

// ---------------- cost-pair math (single-div GIoU, FADD.SAT clamps) ----------
__device__ __forceinline__ float cost_pair(const float* __restrict__ spred, int ii,
                                           float prob, float4 tc, float4 txy, float tarea) {
    float4 pc  = *(const float4*)&spred[ii * 12];
    float4 pxy = *(const float4*)&spred[ii * 12 + 4];
    float  parea = spred[ii * 12 + 8];

    float l1 = fabsf(pc.x - tc.x) + fabsf(pc.y - tc.y)
             + fabsf(pc.z - tc.z) + fabsf(pc.w - tc.w);

    float ltx = fmaxf(pxy.x, txy.x), lty = fmaxf(pxy.y, txy.y);
    float rbx = fminf(pxy.z, txy.z), rby = fminf(pxy.w, txy.w);
    float iw = __saturatef(rbx - ltx), ih = __saturatef(rby - lty);
    float inter = iw * ih;
    float uni = parea + tarea - inter;

    float ex0 = fminf(pxy.x, txy.x), ey0 = fminf(pxy.y, txy.y);
    float ex1 = fmaxf(pxy.z, txy.z), ey1 = fmaxf(pxy.w, txy.w);
    float earea = (ex1 - ex0) * (ey1 - ey0);

    float s = __fdividef(fmaf(uni, uni, inter * earea), uni * earea);
    return fmaf(-2.0f, s, fmaf(5.0f, l1, 2.0f - prob));
}

// ---------------- cost tile (diag or off-diag) --------------------------------
__device__ __forceinline__ void cost_tile(int itile, int jtile, bool diag,
                                          float* __restrict__ outC,
                                          unsigned char* sm) {
    float* sprob = (float*)sm;                  // 5888 B
    float* spred = (float*)(sm + 5888);         // 768 B
    float* stile = (float*)(sm + 6656);         // 256*17*4 (diag only)

    int tid = threadIdx.x;
    int jg  = (jtile << 8) + tid;
    int i0  = itile * 16;

    for (int k = tid; k < 16 * NC; k += 256) sprob[k] = g_prob[i0 * NC + k];
    for (int k = tid; k < 16 * 12; k += 256) spred[k] = g_predf[i0 * 12 + k];
    __syncthreads();

    const float4* tf = (const float4*)&g_tgtf[jg * 12];
    float4 tc = tf[0];
    float4 txy = tf[1];
    float  tarea = g_tgtf[jg * 12 + 8];
    int    lab   = g_tlab[jg];
    const float* prp = sprob + lab;

    float* op = outC + (size_t)i0 * NT + jg;

    if (!diag) {
        #pragma unroll 4
        for (int ii = 0; ii < 16; ii++) {
            float c = cost_pair(spred, ii, prp[ii * NC], tc, txy, tarea);
            __stcs(&op[(size_t)ii * NT], c);     // streaming store
        }
        return;
    }

    int b = jtile;
    int iiA = b * QN - i0;           if (iiA < 0)  iiA = 0;
    int iiB = b * QN + QN - 1 - i0;  if (iiB > 15) iiB = 15;

    long long bestkey = I64_INF;
    #pragma unroll 4
    for (int ii = 0; ii < 16; ii++) {
        float c = cost_pair(spred, ii, prp[ii * NC], tc, txy, tarea);
        op[(size_t)ii * NT] = c;
        stile[tid * 17 + ii] = c;
        if (ii >= iiA && ii <= iiB) {
            long long ci = llrintf(c * FP_SCALE_F);
            int q = i0 + ii - b * QN;
            long long key = ((ci + KEY_BIAS) << 10) | (long long)q;
            if (key < bestkey) bestkey = key;
        }
    }
    if (bestkey != I64_INF) atomicMin(&g_rowkey[jg], bestkey);
    __syncthreads();

    for (int e = tid; e < 256 * 16; e += 256) {
        int t = e >> 4, ii = e & 15;
        if (ii >= iiA && ii <= iiB) {
            int q = i0 + ii - b * QN;
            g_Ci[(size_t)((b << 8) + t) * QN + q] = llrintf(stile[t * 17 + ii] * FP_SCALE_F);
        }
    }

    __threadfence();
    __syncthreads();
    if (tid == 0) atomicAdd(&g_diag_cnt[b], 1);
}

// ---------------- cp.async self-slice row prefetch ---------------------------
// Each thread copies ITS OWN 4 row elements (8B each) so per-thread
// cp.async.wait_group makes them visible without a block barrier.
__device__ __forceinline__ void cp_row(unsigned int dbase, const long long* src, int tid) {
    unsigned int d = dbase + tid * 8;
    asm volatile("cp.async.ca.shared.global [%0], [%1], 8;" :: "r"(d),        "l"(src + tid));
    asm volatile("cp.async.ca.shared.global [%0], [%1], 8;" :: "r"(d + 2048), "l"(src + tid + 256));
    asm volatile("cp.async.ca.shared.global [%0], [%1], 8;" :: "r"(d + 4096), "l"(src + tid + 512));
    asm volatile("cp.async.ca.shared.global [%0], [%1], 8;" :: "r"(d + 6144), "l"(src + tid + 768));
    asm volatile("cp.async.commit_group;" ::: "memory");
}

// ---------------- LSA: seed -> augrowred (prefetched) -> Dijkstra ------------
__device__ void lsa_block(int b, float* __restrict__ out, unsigned char* sm) {
    const int tid  = threadIdx.x;
    const int lane = tid & 31;
    const int wrp  = tid >> 5;
    const long long* Cb = g_Ci + (size_t)b * TN * QN;
    const bool has3 = (tid + 768) < QN;
    const int j3 = tid + 768;

    long long* sv    = (long long*)sm;            // 7200
    long long* su    = (long long*)(sm + 7200);   // 2048
    long long* w1    = (long long*)(sm + 9248);   // 64
    long long* w2    = (long long*)(sm + 9312);   // 64
    long long* wkey  = (long long*)(sm + 9376);   // 128
    int*       sp    = (int*)(sm + 9504);         // 3600
    int*       sway  = (int*)(sm + 13104);        // 3600
    int*       spend = (int*)(sm + 16704);        // 4096
    int*       sq    = (int*)(sm + 20800);        // 32
    const unsigned int bufaddr = (unsigned int)__cvta_generic_to_shared(sm + BUF_OFF);

    // wait for this batch's diagonal tiles
    if (tid == 0) {
        while (*(volatile int*)&g_diag_cnt[b] < 57) __nanosleep(100);
    }
    __syncthreads();
    __threadfence();

    for (int j = tid; j < QN; j += 256) { sp[j] = 0; sv[j] = 0; }
    for (int i = tid; i < TN; i += 256)
        su[i] = (g_rowkey[b * TN + i] >> 10) - KEY_BIAS;
    __syncthreads();

    // greedy seeding
    if (tid == 0) {
        int np = 0;
        for (int i = 0; i < TN; i++) {
            int j = (int)(g_rowkey[b * TN + i] & 1023LL);
            if (sp[j] == 0) sp[j] = i + 1;
            else spend[np++] = i;
        }
        sq[0] = 0; sq[1] = np; sq[2] = -1;
    }
    __syncthreads();

    // initial prefetch of first pending row
    int pf = -1, pfbuf = 0;
    {
        int qh = sq[0], qt = sq[1];
        if (qh < qt) { pf = spend[qh]; cp_row(bufaddr, Cb + (size_t)pf * QN, tid); }
    }

    // --- augmenting row reduction with cp.async row prefetch ---
    int iter = 0;
    while (true) {
        int qh = sq[0], qt = sq[1];            // ordered by B2 / initial barrier
        if (qh >= qt || iter >= 740) break;
        iter++;
        int i = spend[qh];
        bool early = (qh + 1 < qt);
        long long r0, r1, r2, r3;
        if (early) {                            // next row known: issue a full iter ahead
            int pnx = spend[qh + 1];
            cp_row(bufaddr + ((unsigned)(pfbuf ^ 1) << 13), Cb + (size_t)pnx * QN, tid);
            if (pf == i) {
                asm volatile("cp.async.wait_group 1;" ::: "memory");
                const long long* B = (const long long*)(sm + BUF_OFF + (pfbuf << 13));
                r0 = B[tid]; r1 = B[tid + 256]; r2 = B[tid + 512]; r3 = has3 ? B[tid + 768] : 0;
            } else {
                const long long* row = Cb + (size_t)i * QN;
                r0 = row[tid]; r1 = row[tid + 256]; r2 = row[tid + 512]; r3 = has3 ? row[j3] : 0;
            }
            pf = pnx; pfbuf ^= 1;
        } else {
            if (pf == i) {
                asm volatile("cp.async.wait_group 0;" ::: "memory");
                const long long* B = (const long long*)(sm + BUF_OFF + (pfbuf << 13));
                r0 = B[tid]; r1 = B[tid + 256]; r2 = B[tid + 512]; r3 = has3 ? B[tid + 768] : 0;
            } else {
                const long long* row = Cb + (size_t)i * QN;
                r0 = row[tid]; r1 = row[tid + 256]; r2 = row[tid + 512]; r3 = has3 ? row[j3] : 0;
            }
            pf = -1;
        }

        // keys + reduce
        long long k1, k2;
        {
            long long c0 = ((r0 - sv[tid])       << 10) | (long long)tid;
            long long c1 = ((r1 - sv[tid + 256]) << 10) | (long long)(tid + 256);
            long long c2 = ((r2 - sv[tid + 512]) << 10) | (long long)(tid + 512);
            k1 = c0 < c1 ? c0 : c1;  k2 = c0 < c1 ? c1 : c0;
            if (c2 < k1) { k2 = k1; k1 = c2; } else if (c2 < k2) k2 = c2;
            if (has3) {
                long long c3 = ((r3 - sv[j3]) << 10) | (long long)j3;
                if (c3 < k1) { k2 = k1; k1 = c3; } else if (c3 < k2) k2 = c3;
            }
        }
        #pragma unroll
        for (int o = 16; o; o >>= 1) {
            long long o1 = __shfl_down_sync(0xffffffffu, k1, o);
            long long o2 = __shfl_down_sync(0xffffffffu, k2, o);
            long long n1 = k1 < o1 ? k1 : o1;
            long long hi = k1 < o1 ? o1 : k1;
            long long lo2 = k2 < o2 ? k2 : o2;
            k1 = n1; k2 = hi < lo2 ? hi : lo2;
        }
        if (lane == 0) { w1[wrp] = k1; w2[wrp] = k2; }
        __syncthreads();                        // B1
        if (tid == 0) {
            long long m1 = w1[0], m2 = w2[0];
            #pragma unroll
            for (int w = 1; w < 8; w++) {
                long long a1 = w1[w], a2 = w2[w];
                long long n1 = m1 < a1 ? m1 : a1;
                long long hi = m1 < a1 ? a1 : m1;
                long long lo2 = m2 < a2 ? m2 : a2;
                m1 = n1; m2 = hi < lo2 ? hi : lo2;
            }
            int j1 = (int)(m1 & 1023LL);
            long long u1 = m1 >> 10, u2 = m2 >> 10;
            int i0 = sp[j1];
            if (u1 < u2) sv[j1] -= (u2 - u1);
            else if (i0 > 0) { j1 = (int)(m2 & 1023LL); i0 = sp[j1]; }
            sp[j1] = i + 1;
            su[i] = u2;
            sq[0] = qh + 1;
            if (i0 > 0) { spend[qt] = i0 - 1; sq[1] = qt + 1; }
            sq[2] = (!early && i0 > 0) ? (i0 - 1) : -1;   // chain prediction (exact)
        }
        __syncthreads();                        // B2
        if (!early) {
            int pn = sq[2];
            if (pn >= 0) {
                pfbuf ^= 1; pf = pn;
                cp_row(bufaddr + ((unsigned)pfbuf << 13), Cb + (size_t)pn * QN, tid);
            }
        }
    }
    __syncthreads();

    // --- Dijkstra shortest augmenting paths for leftovers ---
    long long v[4];
    v[0] = sv[tid]; v[1] = sv[tid + 256]; v[2] = sv[tid + 512];
    v[3] = has3 ? sv[j3] : 0;

    int qh = sq[0], qt = sq[1];
    for (int pi = qh; pi < qt; pi++) {
        int istart = spend[pi];
        long long dist[4];
        dist[0] = dist[1] = dist[2] = dist[3] = DINF_D;
        unsigned usedm = 0;
        int buf = 0;

        long long bv = 0;
        int i0r = istart, j0 = -1;
        int sink; long long minVal;

        while (true) {
            long long base = bv - su[i0r];
            const long long* row = Cb + (size_t)i0r * QN;

            long long c0 = base + row[tid] - v[0];
            if (c0 < dist[0]) { dist[0] = c0; sway[tid] = j0; }
            long long c1 = base + row[tid + 256] - v[1];
            if (c1 < dist[1]) { dist[1] = c1; sway[tid + 256] = j0; }
            long long c2 = base + row[tid + 512] - v[2];
            if (c2 < dist[2]) { dist[2] = c2; sway[tid + 512] = j0; }
            if (has3) {
                long long c3 = base + row[j3] - v[3];
                if (c3 < dist[3]) { dist[3] = c3; sway[j3] = j0; }
            }
            long long k0 = (usedm & 1u) ? KEY_MAX : ((dist[0] << 10) | (long long)tid);
            long long k1 = (usedm & 2u) ? KEY_MAX : ((dist[1] << 10) | (long long)(tid + 256));
            long long k2 = (usedm & 4u) ? KEY_MAX : ((dist[2] << 10) | (long long)(tid + 512));
            long long k3 = (!has3 || (usedm & 8u)) ? KEY_MAX : ((dist[3] << 10) | (long long)j3);
            long long lb = k0 < k1 ? k0 : k1;
            long long lc = k2 < k3 ? k2 : k3;
            lb = lb < lc ? lb : lc;
            #pragma unroll
            for (int o = 16; o; o >>= 1) {
                long long ov = __shfl_down_sync(0xffffffffu, lb, o);
                lb = ov < lb ? ov : lb;
            }
            if (lane == 0) wkey[buf * 8 + wrp] = lb;
            __syncthreads();
            long long mk = wkey[buf * 8];
            #pragma unroll
            for (int w = 1; w < 8; w++) { long long a = wkey[buf * 8 + w]; mk = a < mk ? a : mk; }
            buf ^= 1;

            int jj = (int)(mk & 1023LL);
            bv = mk >> 10;
            if ((jj & 255) == tid) usedm |= 1u << (jj >> 8);
            int r = sp[jj];
            if (r == 0) { sink = jj; minVal = bv; break; }
            j0 = jj; i0r = r - 1;
        }

        #pragma unroll
        for (int k = 0; k < 4; k++) {
            if (usedm & (1u << k)) {
                int j = tid + (k << 8);
                long long d = dist[k];
                v[k] += d - minVal;
                su[sp[j] - 1] += minVal - d;
            }
        }
        __syncthreads();
        if (tid == 0) {
            su[istart] += minVal;
            int j = sink;
            while (true) {
                int jp = sway[j];
                if (jp < 0) { sp[j] = istart + 1; break; }
                sp[j] = sp[jp];
                j = jp;
            }
        }
        __syncthreads();
    }

    if (tid == 0) {
        float* rows = out + (size_t)C_ELEMS + b * TN;
        float* cols = out + (size_t)C_ELEMS + NT + b * TN;
        int k = 0;
        for (int j = 0; j < QN; j++) {
            if (sp[j]) { rows[k] = (float)j; cols[k] = (float)(sp[j] - 1); k++; }
        }
    }
}

// ---------------- fully fused kernel ------------------------------------------
__global__ void __launch_bounds__(256, 6) fused_k(float* __restrict__ outC) {
    __shared__ __align__(16) unsigned char smraw[SMEM_BYTES];
    int bid = blockIdx.x;

    if (bid < 16) { lsa_block(bid, outC, smraw); return; }

    if (bid < 16 + NDIAG) {
        int idx = bid - 16;
        int b = idx / 57;
        int itile = tmin_of(b) + idx % 57;
        cost_tile(itile, b, true, outC, smraw);
        return;
    }

    int e = bid - (16 + NDIAG);
    int itile = e >> 4;
    int jtile = e & 15;
    if (itile >= tmin_of(jtile) && itile <= tmax_of(jtile)) return;
    cost_tile(itile, jtile, false, outC, smraw);
}

// ---------------- launch -----------------------------------------------------
extern "C" void kernel_launch(void* const* d_in, const int* in_sizes, int n_in,
                              void* d_out, int out_size) {
    const float* logits = (const float*)d_in[0];
    const float* pboxes = (const float*)d_in[1];
    const int*   tlab   = (const int*)  d_in[2];
    const float* tbox   = (const float*)d_in[3];
    float* out = (float*)d_out;

    prep_softmax_k<<<57 + 1800, 256>>>(logits, pboxes, tbox, tlab);
    fused_k<<<16 + NDIAG + NQT, 256>>>(out);
}